// round 16
// baseline (speedup 1.0000x reference)
#include <cuda_runtime.h>
#include <cuda_fp16.h>
#include <cstdint>
#include <math.h>

// ---------------------------------------------------------------------------
// CenterRingFormerPlus: ALL GEMMs via single fp16 HMMA per k=16.
// Error model (validated R7-R15): ~3.5e-4 per fp16 GEMM + fp16 intermediates,
// quadrature w/ downstream attenuation => ~6.3e-4 < 1e-3 (deterministic).
// 128x128 CTA tiles, 3-stage cp.async ring with EARLY prefetch issue
// (s+2 loads issued after kk=0's MMAs, overlapping tensor drain), ONE sync
// per stage, 2 CTAs/SM, SW128 swizzle, fused epilogues; mm6+mm7 merged;
// all weight conversions in one launch.
// ---------------------------------------------------------------------------

#define MT 16384
#define NT 1024
#define NELE (16384u * 1024u)

// ---- scratch (device globals; no allocation allowed) ----
__device__ __half g_qf[NELE];                        // queries fp16
__device__ __half g_w1f[1024u*7168u];                // fr_w1^T fp16 [N,K]
__device__ __half g_fc1f[1024u*2048u];               // fc_w1^T fp16
__device__ __half g_gwf[1024u*2048u];                // g_w^T fp16
__device__ __half g_w2f[1024u*1024u];                // fr_w2^T fp16
__device__ __half g_c1f[1024u*1024u];                // tc_w1^T fp16
__device__ __half g_c2f[1024u*1024u];                // tc_w2^T fp16
__device__ __half g_f2f[1024u*1024u];                // fc_w2^T fp16
__device__ __half g_h1f[NELE];                       // h1 fp16
__device__ __half g_xrf16[NELE];                     // x_ring fp16
__device__ __half g_wtf[NELE];                       // weighted fp16
__device__ __half g_t1f[NELE];                       // t1 fp16
__device__ __half g_hff[NELE];                       // h_fc fp16
__device__ __half g_gtf16[NELE];                     // gate fp16
__device__ float g_tpf[NELE];                        // token_proj f32

__constant__ int c_shifts[7] = {1, -1, 0, 2, -2, 4, -4};

enum { A_DIRECT = 0, A_ROLL = 1, A_CONCAT = 2 };
enum { EP_GELU_F16 = 0, EP_F16 = 1, EP_F32 = 2, EP_FINAL = 4 };

// ---------------- helpers ----------------
static __device__ __forceinline__ uint32_t s2u(const void* p) {
    return (uint32_t)__cvta_generic_to_shared(p);
}
static __device__ __forceinline__ void cp16(uint32_t d, const void* s) {
    asm volatile("cp.async.cg.shared.global [%0], [%1], 16;\n" :: "r"(d), "l"(s));
}
static __device__ __forceinline__ void cp_commit() {
    asm volatile("cp.async.commit_group;\n" ::: "memory");
}
static __device__ __forceinline__ void ldm4(uint32_t& r0, uint32_t& r1,
                                            uint32_t& r2, uint32_t& r3, uint32_t a) {
    asm volatile("ldmatrix.sync.aligned.m8n8.x4.shared.b16 {%0,%1,%2,%3}, [%4];"
                 : "=r"(r0), "=r"(r1), "=r"(r2), "=r"(r3) : "r"(a));
}
static __device__ __forceinline__ void mma16816h(float* d, const uint32_t* a,
                                                 const uint32_t* b) {
    asm volatile(
        "mma.sync.aligned.m16n8k16.row.col.f32.f16.f16.f32 "
        "{%0,%1,%2,%3}, {%4,%5,%6,%7}, {%8,%9}, {%0,%1,%2,%3};"
        : "+f"(d[0]), "+f"(d[1]), "+f"(d[2]), "+f"(d[3])
        : "r"(a[0]), "r"(a[1]), "r"(a[2]), "r"(a[3]), "r"(b[0]), "r"(b[1]));
}
static __device__ __forceinline__ float gelu_exact(float x) {
    return 0.5f * x * (1.0f + erff(x * 0.7071067811865476f));
}

// ---------------- fp16 tile loader (BK=64, SW128) ----------------
#define STGH_BYTES 32768
#define TH_A 0
#define TH_B 16384
#define SMEM_DYN_H (1024 + 3 * STGH_BYTES)

template <int ASRC>
static __device__ __forceinline__ void loadh_stage(
    uint32_t buf, const __half* __restrict__ A, const __half* __restrict__ A2,
    const __half* __restrict__ B, int K, int k0, int bm, int bn, int tid)
{
#pragma unroll
    for (int i = 0; i < 4; i++) {
        const int c = tid + i * 256;
        const int r = c >> 3, ch = c & 7;
        const uint32_t bo = (uint32_t)(r * 128 + ch * 16);
        const uint32_t sw = bo ^ ((bo >> 3) & 0x70);

        const __half* pa;
        size_t aoff;
        if (ASRC == A_ROLL) {
            const int sh = c_shifts[k0 >> 10];
            const int m = bm + r, bb = m >> 11, nn = m & 2047;
            const int src = (nn - sh) & 2047;
            aoff = ((size_t)((bb << 11) | src)) * 1024u + (size_t)((k0 & 1023) + ch * 8);
            pa = A;
        } else if (ASRC == A_CONCAT) {
            pa = (k0 < 1024) ? A : A2;
            aoff = (size_t)(bm + r) * 1024u + (size_t)((k0 & 1023) + ch * 8);
        } else {  // A_DIRECT
            pa = A;
            aoff = (size_t)(bm + r) * (size_t)K + (size_t)(k0 + ch * 8);
        }
        cp16(buf + TH_A + sw, pa + aoff);

        const size_t boff = (size_t)(bn + r) * (size_t)K + (size_t)(k0 + ch * 8);
        cp16(buf + TH_B + sw, B + boff);
    }
}

static __device__ __forceinline__ void ldfragh(
    uint32_t buf, int kk, int wm, int wn,
    int a_row, int a_kb, int b_row, int b_kb,
    uint32_t (*af)[4], uint32_t (*bf)[2])
{
#pragma unroll
    for (int p = 0; p < 2; p++) {
        const uint32_t bo = (uint32_t)((wn + p * 16 + b_row) * 128 + kk * 32 + b_kb);
        const uint32_t sw = bo ^ ((bo >> 3) & 0x70);
        ldm4(bf[2*p][0], bf[2*p][1], bf[2*p+1][0], bf[2*p+1][1], buf + TH_B + sw);
    }
#pragma unroll
    for (int mt = 0; mt < 4; mt++) {
        const uint32_t bo = (uint32_t)((wm + mt * 16 + a_row) * 128 + kk * 32 + a_kb);
        const uint32_t sw = bo ^ ((bo >> 3) & 0x70);
        ldm4(af[mt][0], af[mt][1], af[mt][2], af[mt][3], buf + TH_A + sw);
    }
}

// ---------------- mainloop body (shared) ----------------
template <int ASRC>
static __device__ __forceinline__ void mm_mainloop(
    uint32_t bufbase, const __half* __restrict__ A, const __half* __restrict__ A2,
    const __half* __restrict__ B, int K, int bm, int bn, int tid,
    int wm, int wn, int lane, float (*acc)[4][4])
{
    const int nst = K >> 6;

    loadh_stage<ASRC>(bufbase,              A, A2, B, K, 0,  bm, bn, tid);
    cp_commit();
    loadh_stage<ASRC>(bufbase + STGH_BYTES, A, A2, B, K, 64, bm, bn, tid);
    cp_commit();

    const int a_row = lane & 15;
    const int a_kb  = ((lane >> 4) & 1) * 16;
    const int b_row = (lane & 7) + ((lane >> 4) & 1) * 8;
    const int b_kb  = ((lane >> 3) & 1) * 16;

    uint32_t af[4][4], bf[4][2];

    int cur = 0;
    for (int s = 0; s < nst; s++) {
        if (s < nst - 1) asm volatile("cp.async.wait_group 1;" ::: "memory");
        else             asm volatile("cp.async.wait_group 0;" ::: "memory");
        __syncthreads();   // stage s visible AND buffer (s-1) fully consumed

        const uint32_t buf = bufbase + (uint32_t)cur * STGH_BYTES;

        // kk = 0: fragments + MMAs first, giving the tensor pipe a head start
        ldfragh(buf, 0, wm, wn, a_row, a_kb, b_row, b_kb, af, bf);
#pragma unroll
        for (int mt = 0; mt < 4; mt++)
#pragma unroll
            for (int nt = 0; nt < 4; nt++)
                mma16816h(acc[mt][nt], af[mt], bf[nt]);

        // EARLY prefetch: issue stage s+2 loads now (its buffer — consumed at
        // s-1 — is free per the top-of-stage sync); LSU issue burst overlaps
        // the tensor-pipe drain of kk=1..3 instead of delaying next stage.
        if (s + 2 < nst) {
            int nb = cur + 2; if (nb >= 3) nb -= 3;
            loadh_stage<ASRC>(bufbase + (uint32_t)nb * STGH_BYTES,
                              A, A2, B, K, (s + 2) * 64, bm, bn, tid);
            cp_commit();
        }

#pragma unroll
        for (int kk = 1; kk < 4; kk++) {
            ldfragh(buf, kk, wm, wn, a_row, a_kb, b_row, b_kb, af, bf);
#pragma unroll
            for (int mt = 0; mt < 4; mt++)
#pragma unroll
                for (int nt = 0; nt < 4; nt++)
                    mma16816h(acc[mt][nt], af[mt], bf[nt]);
        }

        if (++cur == 3) cur = 0;
    }
}

// ---------------- fp16 single-MMA GEMM (mm1,2,3,4,8) ------------------------
template <int ASRC, int EPI>
__global__ __launch_bounds__(256, 2)
void mmh_k(const __half* __restrict__ A, const __half* __restrict__ A2,
           const __half* __restrict__ B,
           const float* __restrict__ bias, int K,
           float* __restrict__ Of, __half* __restrict__ Oh16,
           const __half* __restrict__ e_gate, const __half* __restrict__ e_xr)
{
    extern __shared__ char smraw[];
    const uint32_t bufbase = (s2u(smraw) + 1023u) & ~1023u;
    const int tid = threadIdx.x, wid = tid >> 5, lane = tid & 31;
    const int bn = blockIdx.x * 128, bm = blockIdx.y * 128;
    const int wm = (wid >> 2) * 64, wn = (wid & 3) * 32;

    float acc[4][4][4];
#pragma unroll
    for (int mt = 0; mt < 4; mt++)
#pragma unroll
        for (int nt = 0; nt < 4; nt++)
#pragma unroll
            for (int r = 0; r < 4; r++) acc[mt][nt][r] = 0.0f;

    mm_mainloop<ASRC>(bufbase, A, A2, B, K, bm, bn, tid, wm, wn, lane, acc);

    const int qr = lane >> 2;
    const int qc = (lane & 3) * 2;
#pragma unroll
    for (int mt = 0; mt < 4; mt++) {
#pragma unroll
        for (int nt = 0; nt < 4; nt++) {
            const int col = bn + wn + nt * 8 + qc;
            const float2 bs = *(const float2*)(bias + col);
#pragma unroll
            for (int h = 0; h < 2; h++) {
                const int row = bm + wm + mt * 16 + qr + h * 8;
                const size_t off = (size_t)row * 1024u + (size_t)col;
                float v0 = acc[mt][nt][2*h]     + bs.x;
                float v1 = acc[mt][nt][2*h + 1] + bs.y;
                if (EPI == EP_GELU_F16) {
                    v0 = gelu_exact(v0);  v1 = gelu_exact(v1);
                    *(__half2*)(Oh16 + off) = __floats2half2_rn(v0, v1);
                } else if (EPI == EP_F16) {
                    *(__half2*)(Oh16 + off) = __floats2half2_rn(v0, v1);
                } else if (EPI == EP_F32) {
                    *(float2*)(Of + off) = make_float2(v0, v1);
                } else {  // EP_FINAL
                    const float2 g = __half22float2(*(const __half2*)(e_gate + off));
                    const float2 x = __half22float2(*(const __half2*)(e_xr + off));
                    *(float2*)(Of + off) = make_float2(
                        g.x * v0 + (1.0f - g.x) * x.x,
                        g.y * v1 + (1.0f - g.y) * x.y);
                }
            }
        }
    }
}

// ---------------- merged mm6+mm7 kernel (same A, two B's) -------------------
__global__ __launch_bounds__(256, 2)
void mmh67_k(const __half* __restrict__ Axr, const __half* __restrict__ Awt,
             const __half* __restrict__ Bgw, const __half* __restrict__ Bfc,
             const float* __restrict__ bias_g, const float* __restrict__ bias_fc,
             __half* __restrict__ gate_out, __half* __restrict__ hfc_out)
{
    extern __shared__ char smraw[];
    const uint32_t bufbase = (s2u(smraw) + 1023u) & ~1023u;
    const int tid = threadIdx.x, wid = tid >> 5, lane = tid & 31;
    const bool is_fc = blockIdx.x >= 8;
    const int bn = (blockIdx.x & 7) * 128, bm = blockIdx.y * 128;
    const int wm = (wid >> 2) * 64, wn = (wid & 3) * 32;
    const __half* B = is_fc ? Bfc : Bgw;
    const float* bias = is_fc ? bias_fc : bias_g;

    float acc[4][4][4];
#pragma unroll
    for (int mt = 0; mt < 4; mt++)
#pragma unroll
        for (int nt = 0; nt < 4; nt++)
#pragma unroll
            for (int r = 0; r < 4; r++) acc[mt][nt][r] = 0.0f;

    mm_mainloop<A_CONCAT>(bufbase, Axr, Awt, B, 2048, bm, bn, tid, wm, wn, lane, acc);

    const int qr = lane >> 2;
    const int qc = (lane & 3) * 2;
#pragma unroll
    for (int mt = 0; mt < 4; mt++) {
#pragma unroll
        for (int nt = 0; nt < 4; nt++) {
            const int col = bn + wn + nt * 8 + qc;
            const float2 bs = *(const float2*)(bias + col);
#pragma unroll
            for (int h = 0; h < 2; h++) {
                const int row = bm + wm + mt * 16 + qr + h * 8;
                const size_t off = (size_t)row * 1024u + (size_t)col;
                float v0 = acc[mt][nt][2*h]     + bs.x;
                float v1 = acc[mt][nt][2*h + 1] + bs.y;
                if (is_fc) {
                    v0 = gelu_exact(v0);  v1 = gelu_exact(v1);
                    *(__half2*)(hfc_out + off) = __floats2half2_rn(v0, v1);
                } else {
                    v0 = 1.0f / (1.0f + expf(-v0));
                    v1 = 1.0f / (1.0f + expf(-v1));
                    *(__half2*)(gate_out + off) = __floats2half2_rn(v0, v1);
                }
            }
        }
    }
}

// ---------------- conversions ----------------
__global__ void qhconv_k(const float* __restrict__ Q, __half* __restrict__ H, int n)
{
    for (int i = blockIdx.x * 256 + threadIdx.x; i * 4 < n; i += gridDim.x * 256) {
        const float4 a = *(const float4*)(Q + i * 4);
        __half2 h0 = __floats2half2_rn(a.x, a.y);
        __half2 h1 = __floats2half2_rn(a.z, a.w);
        uint2 v;
        v.x = *(uint32_t*)&h0;  v.y = *(uint32_t*)&h1;
        *(uint2*)(H + i * 4) = v;
    }
}

// ALL weight transpose-converts in ONE launch.
// grid = (480, 32): blockIdx.x = stacked k-tile index, blockIdx.y = n-tile.
__global__ void wconvall_k(
    const float* W1, __half* T1, const float* Wfc1, __half* Tfc1,
    const float* Wgw, __half* Tgw, const float* Ww2, __half* Tw2,
    const float* Wc1, __half* Tc1, const float* Wc2, __half* Tc2,
    const float* Wf2, __half* Tf2)
{
    __shared__ float t[32 * 33];
    const int kt = blockIdx.x;
    const float* W; __half* T; int K, kl;
    if (kt < 224)      { W = W1;   T = T1;   K = 7168; kl = kt; }
    else if (kt < 288) { W = Wfc1; T = Tfc1; K = 2048; kl = kt - 224; }
    else if (kt < 352) { W = Wgw;  T = Tgw;  K = 2048; kl = kt - 288; }
    else if (kt < 384) { W = Ww2;  T = Tw2;  K = 1024; kl = kt - 352; }
    else if (kt < 416) { W = Wc1;  T = Tc1;  K = 1024; kl = kt - 384; }
    else if (kt < 448) { W = Wc2;  T = Tc2;  K = 1024; kl = kt - 416; }
    else               { W = Wf2;  T = Tf2;  K = 1024; kl = kt - 448; }

    const int n0 = blockIdx.y * 32, k0 = kl * 32;
    const int tx = threadIdx.x, ty = threadIdx.y;
#pragma unroll
    for (int i = 0; i < 4; i++)
        t[(ty + i * 8) * 33 + tx] = W[(size_t)(k0 + ty + i * 8) * 1024u + n0 + tx];
    __syncthreads();
#pragma unroll
    for (int i = 0; i < 4; i++) {
        const size_t o = (size_t)(n0 + ty + i * 8) * (size_t)K + k0 + tx;
        T[o] = __float2half_rn(t[tx * 33 + ty + i * 8]);
    }
}

// ---------------- cluster softmax (fp16 weighted out) ----------------------
__global__ __launch_bounds__(256)
void cluster_k(const float* __restrict__ tproj, const float* __restrict__ centers,
               __half* __restrict__ wtf)
{
    __shared__ float sc[4 * 1024];
    const int tid = threadIdx.x;
    for (int i = tid * 4; i < 4096; i += 256 * 4)
        *(float4*)&sc[i] = *(const float4*)&centers[i];
    __syncthreads();

    const int warp = tid >> 5, lane = tid & 31;
    const size_t row = (size_t)blockIdx.x * 8 + warp;
    const float* tp = tproj + row * 1024u;

    float d0 = 0.f, d1 = 0.f, d2 = 0.f, d3 = 0.f;
    for (int d = lane * 4; d < 1024; d += 128) {
        float4 t  = *(const float4*)(tp + d);
        float4 c0 = *(const float4*)(sc + d);
        float4 c1 = *(const float4*)(sc + 1024 + d);
        float4 c2 = *(const float4*)(sc + 2048 + d);
        float4 c3 = *(const float4*)(sc + 3072 + d);
        d0 += t.x*c0.x + t.y*c0.y + t.z*c0.z + t.w*c0.w;
        d1 += t.x*c1.x + t.y*c1.y + t.z*c1.z + t.w*c1.w;
        d2 += t.x*c2.x + t.y*c2.y + t.z*c2.z + t.w*c2.w;
        d3 += t.x*c3.x + t.y*c3.y + t.z*c3.z + t.w*c3.w;
    }
#pragma unroll
    for (int off = 16; off > 0; off >>= 1) {
        d0 += __shfl_xor_sync(0xffffffffu, d0, off);
        d1 += __shfl_xor_sync(0xffffffffu, d1, off);
        d2 += __shfl_xor_sync(0xffffffffu, d2, off);
        d3 += __shfl_xor_sync(0xffffffffu, d3, off);
    }
    const float mx = fmaxf(fmaxf(d0, d1), fmaxf(d2, d3));
    const float e0 = expf(d0 - mx), e1 = expf(d1 - mx),
                e2 = expf(d2 - mx), e3 = expf(d3 - mx);
    const float inv = 1.0f / (e0 + e1 + e2 + e3);
    const float w0 = e0*inv, w1 = e1*inv, w2 = e2*inv, w3 = e3*inv;

    for (int d = lane * 4; d < 1024; d += 128) {
        float4 c0 = *(const float4*)(sc + d);
        float4 c1 = *(const float4*)(sc + 1024 + d);
        float4 c2 = *(const float4*)(sc + 2048 + d);
        float4 c3 = *(const float4*)(sc + 3072 + d);
        float o0 = w0*c0.x + w1*c1.x + w2*c2.x + w3*c3.x;
        float o1 = w0*c0.y + w1*c1.y + w2*c2.y + w3*c3.y;
        float o2 = w0*c0.z + w1*c1.z + w2*c2.z + w3*c3.z;
        float o3 = w0*c0.w + w1*c1.w + w2*c2.w + w3*c3.w;
        __half2 p0 = __floats2half2_rn(o0, o1);
        __half2 p1 = __floats2half2_rn(o2, o3);
        uint2 v;
        v.x = *(uint32_t*)&p0;  v.y = *(uint32_t*)&p1;
        *(uint2*)(wtf + row * 1024u + d) = v;
    }
}

// ---------------- launch ----------------
extern "C" void kernel_launch(void* const* d_in, const int* in_sizes, int n_in,
                              void* d_out, int out_size)
{
    const float* queries = (const float*)d_in[0];
    const float* fr_w1   = (const float*)d_in[1];
    const float* fr_b1   = (const float*)d_in[2];
    const float* fr_w2   = (const float*)d_in[3];
    const float* fr_b2   = (const float*)d_in[4];
    const float* tc_w1   = (const float*)d_in[5];
    const float* tc_b1   = (const float*)d_in[6];
    const float* tc_w2   = (const float*)d_in[7];
    const float* tc_b2   = (const float*)d_in[8];
    const float* centers = (const float*)d_in[9];
    const float* fc_w1   = (const float*)d_in[10];
    const float* fc_b1   = (const float*)d_in[11];
    const float* fc_w2   = (const float*)d_in[12];
    const float* fc_b2   = (const float*)d_in[13];
    const float* g_w     = (const float*)d_in[14];
    const float* g_b     = (const float*)d_in[15];
    float* out = (float*)d_out;

#define SYM(p, s) { void* _t; cudaGetSymbolAddress(&_t, s); p = (decltype(p))_t; }
    __half *qf, *w1f, *fc1f, *gwf, *w2f, *c1f, *c2f, *f2f;
    __half *h1f, *xrf16, *wtf, *t1f, *hff, *gtf16;
    float *tpf;
    SYM(qf, g_qf);     SYM(w1f, g_w1f);
    SYM(fc1f, g_fc1f); SYM(gwf, g_gwf);
    SYM(w2f, g_w2f);   SYM(c1f, g_c1f);
    SYM(c2f, g_c2f);   SYM(f2f, g_f2f);
    SYM(h1f, g_h1f);   SYM(xrf16, g_xrf16);
    SYM(wtf, g_wtf);   SYM(t1f, g_t1f);   SYM(hff, g_hff);
    SYM(gtf16, g_gtf16); SYM(tpf, g_tpf);
#undef SYM

    cudaFuncSetAttribute(mmh_k<A_ROLL,   EP_GELU_F16>, cudaFuncAttributeMaxDynamicSharedMemorySize, SMEM_DYN_H);
    cudaFuncSetAttribute(mmh_k<A_DIRECT, EP_F16>,      cudaFuncAttributeMaxDynamicSharedMemorySize, SMEM_DYN_H);
    cudaFuncSetAttribute(mmh_k<A_DIRECT, EP_GELU_F16>, cudaFuncAttributeMaxDynamicSharedMemorySize, SMEM_DYN_H);
    cudaFuncSetAttribute(mmh_k<A_DIRECT, EP_F32>,      cudaFuncAttributeMaxDynamicSharedMemorySize, SMEM_DYN_H);
    cudaFuncSetAttribute(mmh_k<A_DIRECT, EP_FINAL>,    cudaFuncAttributeMaxDynamicSharedMemorySize, SMEM_DYN_H);
    cudaFuncSetAttribute(mmh67_k, cudaFuncAttributeMaxDynamicSharedMemorySize, SMEM_DYN_H);

    dim3 wcb(32, 8);

    // ---- conversions (2 launches total) ----
    qhconv_k<<<2048, 256>>>(queries, qf, (int)NELE);
    wconvall_k<<<dim3(480, 32), wcb>>>(fr_w1, w1f, fc_w1, fc1f, g_w, gwf,
                                       fr_w2, w2f, tc_w1, c1f, tc_w2, c2f,
                                       fc_w2, f2f);

    dim3 grid(8, 128), block(256);

    // mm1: h1 = gelu(fusion @ fr_w1 + fr_b1)   K=7168, roll-gathered
    mmh_k<A_ROLL, EP_GELU_F16><<<grid, block, SMEM_DYN_H>>>(
        qf, nullptr, w1f, fr_b1, 7168, nullptr, h1f, nullptr, nullptr);
    // mm2: x_ring = h1 @ fr_w2 + fr_b2   -> fp16
    mmh_k<A_DIRECT, EP_F16><<<grid, block, SMEM_DYN_H>>>(
        h1f, nullptr, w2f, fr_b2, 1024, nullptr, xrf16, nullptr, nullptr);
    // mm3: t1 = gelu(x_ring @ tc_w1 + tc_b1)   -> fp16
    mmh_k<A_DIRECT, EP_GELU_F16><<<grid, block, SMEM_DYN_H>>>(
        xrf16, nullptr, c1f, tc_b1, 1024, nullptr, t1f, nullptr, nullptr);
    // mm4: token_proj = t1 @ tc_w2 + tc_b2   -> f32
    mmh_k<A_DIRECT, EP_F32><<<grid, block, SMEM_DYN_H>>>(
        t1f, nullptr, c2f, tc_b2, 1024, tpf, nullptr, nullptr, nullptr);
    // mm5: weighted = softmax(tp @ centers^T) @ centers  -> fp16
    cluster_k<<<MT / 8, 256>>>(tpf, centers, wtf);
    // mm6+mm7 merged: gate (sigmoid->fp16) and h_fc (gelu->fp16)
    mmh67_k<<<dim3(16, 128), block, SMEM_DYN_H>>>(
        xrf16, wtf, gwf, fc1f, g_b, fc_b1, gtf16, hff);
    // mm8: out = gate * (h_fc @ fc_w2 + fc_b2) + (1-gate) * x_ring
    mmh_k<A_DIRECT, EP_FINAL><<<grid, block, SMEM_DYN_H>>>(
        hff, nullptr, f2f, fc_b2, 1024, out, nullptr, gtf16, xrf16);
}